// round 2
// baseline (speedup 1.0000x reference)
#include <cuda_runtime.h>
#include <cuda_bf16.h>
#include <cstdint>

// out[n, d] = input[n, d] * W[d]
// N = 16384, D = 4096, fp32. Pure streaming: 256MB in + 256MB out.
// HBM-bound; goal is saturating DRAM with 128-bit accesses.

static constexpr int N_ROWS = 16384;
static constexpr int D_COLS = 4096;
static constexpr int D4 = D_COLS / 4;            // 1024 float4 per row (power of 2)
static constexpr long long TOTAL4 = (long long)N_ROWS * D4;  // 16,777,216 float4

__global__ void __launch_bounds__(256) diag_scale_kernel(
    const float4* __restrict__ in,
    const float4* __restrict__ w,     // D/4 float4, L2/L1 resident
    float4* __restrict__ out)
{
    // 2 float4 per thread to raise MLP (front-batched loads).
    unsigned idx = (blockIdx.x * blockDim.x + threadIdx.x) * 2u;

    // idx & (D4-1) gives the float4-column; D4 = 1024 is a power of two.
    float4 a0 = in[idx];
    float4 a1 = in[idx + 1];
    float4 w0 = __ldg(&w[idx & (D4 - 1)]);
    float4 w1 = __ldg(&w[(idx + 1) & (D4 - 1)]);

    float4 r0, r1;
    r0.x = a0.x * w0.x; r0.y = a0.y * w0.y; r0.z = a0.z * w0.z; r0.w = a0.w * w0.w;
    r1.x = a1.x * w1.x; r1.y = a1.y * w1.y; r1.z = a1.z * w1.z; r1.w = a1.w * w1.w;

    out[idx]     = r0;
    out[idx + 1] = r1;
}

extern "C" void kernel_launch(void* const* d_in, const int* in_sizes, int n_in,
                              void* d_out, int out_size) {
    const float4* in = (const float4*)d_in[0];
    const float4* w  = (const float4*)d_in[1];
    float4* out = (float4*)d_out;

    // TOTAL4 / 2 threads, 256 per block: 16,777,216 / 2 / 256 = 32768 blocks.
    // Exact division — no tail handling needed for these fixed shapes.
    int threads = 256;
    long long n_thread = TOTAL4 / 2;
    int blocks = (int)(n_thread / threads);
    diag_scale_kernel<<<blocks, threads>>>(in, w, out);
}